// round 8
// baseline (speedup 1.0000x reference)
#include <cuda_runtime.h>
#include <cstdint>
#include <cstddef>

#define NN     50000
#define NEDGE  800000
#define NDIM   64
#define HDIM   128
#define EDIM   32
#define CH     256   // combined hidden: 128 (node MLP) + 128 (coord MLP)

// ---------------- device scratch (static, no allocation) ----------------
__device__ __align__(16) float g_Pa[(size_t)NN * CH];  // h[n] @ W1[rows 0..63]   (src slice)
__device__ __align__(16) float g_Pb[(size_t)NN * CH];  // h[n] @ W1[rows 64..127] (dst slice)
__device__ __align__(16) float g_We2b[EDIM * CH];      // We2 @ W1[rows 128..159]
__device__ __align__(16) float g_biasH[CH];            // [bn1;bc1] + be2 @ W1_bottom
__device__ int g_src[NEDGE];
__device__ int g_dst[NEDGE];
__device__ int g_is64;

__device__ __forceinline__ float siluf(float v) {
    return v / (1.f + __expf(-v));
}

__device__ __forceinline__ void ld8(float* w, const float* p) {
    float4 a = *(const float4*)p;
    float4 b = *(const float4*)(p + 4);
    w[0]=a.x; w[1]=a.y; w[2]=a.z; w[3]=a.w;
    w[4]=b.x; w[5]=b.y; w[6]=b.z; w[7]=b.w;
}

// ---------------- prep: fold edge-MLP second layer into combined W1 ----------------
__global__ void prep_kernel(const float* __restrict__ We2, const float* __restrict__ be2,
                            const float* __restrict__ Wn1, const float* __restrict__ bn1,
                            const float* __restrict__ Wc1, const float* __restrict__ bc1,
                            const int* __restrict__ ei32)
{
    int tid = blockIdx.x * blockDim.x + threadIdx.x;   // 32 blocks * 256 = 8192 = EDIM*CH
    if (tid < EDIM * CH) {
        int j = tid >> 8;          // 0..31   (edge-hidden index)
        int c = tid & 255;         // 0..255  (combined hidden col)
        float s = 0.f;
        for (int k = 0; k < EDIM; k++) {
            float wb = (c < HDIM) ? Wn1[(2*NDIM + k) * HDIM + c]
                                  : Wc1[(2*NDIM + k) * HDIM + (c - HDIM)];
            s = fmaf(We2[j*EDIM + k], wb, s);
        }
        g_We2b[j*CH + c] = s;
        if (j == 0) {
            float b = (c < HDIM) ? bn1[c] : bc1[c - HDIM];
            for (int k = 0; k < EDIM; k++) {
                float wb = (c < HDIM) ? Wn1[(2*NDIM + k) * HDIM + c]
                                      : Wc1[(2*NDIM + k) * HDIM + (c - HDIM)];
                b = fmaf(be2[k], wb, b);
            }
            g_biasH[c] = b;
        }
    }
    if (tid == 0) {
        // int64 vs int32: node ids < 50000 << 2^31 so int64 layout has all odd
        // 32-bit words zero; 16 random int32 ids all-zero is impossible.
        int z = 0;
        for (int i = 1; i < 32; i += 2) z |= ei32[i];
        g_is64 = (z == 0) ? 1 : 0;
    }
}

// ---------------- index normalization: any dtype -> clamped int32 ----------------
__global__ void index_kernel(const void* __restrict__ ei)
{
    int i = blockIdx.x * blockDim.x + threadIdx.x;
    if (i >= NEDGE) return;
    int s, d;
    if (g_is64) {
        const long long* p = (const long long*)ei;
        s = (int)p[i]; d = (int)p[NEDGE + i];
    } else {
        const int* p = (const int*)ei;
        s = p[i]; d = p[NEDGE + i];
    }
    g_src[i] = min(max(s, 0), NN - 1);   // defensive: never OOB
    g_dst[i] = min(max(d, 0), NN - 1);
}

// ---------------- node precompute: Pa/Pb = h @ W1(top/mid), 1 warp per node ----------------
__global__ __launch_bounds__(256)
void node_kernel(const float* __restrict__ h,
                 const float* __restrict__ Wn1,
                 const float* __restrict__ Wc1)
{
    const int node = (blockIdx.x * blockDim.x + threadIdx.x) >> 5;
    const int l = threadIdx.x & 31;
    if (node >= NN) return;

    const float h0 = h[node*NDIM + l];
    const float h1 = h[node*NDIM + 32 + l];
    // lane l owns combined cols [l*8, l*8+8): first 128 from Wn1, last 128 from Wc1
    const float* WA = (l < 16) ? (Wn1 + l*8) : (Wc1 + l*8 - HDIM);

    float a[8], b[8];
    #pragma unroll
    for (int r = 0; r < 8; r++) { a[r] = 0.f; b[r] = 0.f; }

    #pragma unroll 4
    for (int j = 0; j < 32; j++) {
        const float v0 = __shfl_sync(0xffffffffu, h0, j);
        const float v1 = __shfl_sync(0xffffffffu, h1, j);
        float w[8];
        ld8(w, WA + j*HDIM);                 // W1 row j        -> Pa
        #pragma unroll
        for (int r = 0; r < 8; r++) a[r] = fmaf(v0, w[r], a[r]);
        ld8(w, WA + (32 + j)*HDIM);          // W1 row 32+j     -> Pa
        #pragma unroll
        for (int r = 0; r < 8; r++) a[r] = fmaf(v1, w[r], a[r]);
        ld8(w, WA + (64 + j)*HDIM);          // W1 row 64+j     -> Pb
        #pragma unroll
        for (int r = 0; r < 8; r++) b[r] = fmaf(v0, w[r], b[r]);
        ld8(w, WA + (96 + j)*HDIM);          // W1 row 96+j     -> Pb
        #pragma unroll
        for (int r = 0; r < 8; r++) b[r] = fmaf(v1, w[r], b[r]);
    }

    float* pa = g_Pa + (size_t)node*CH + l*8;
    float* pb = g_Pb + (size_t)node*CH + l*8;
    *(float4*)pa       = make_float4(a[0], a[1], a[2], a[3]);
    *(float4*)(pa + 4) = make_float4(a[4], a[5], a[6], a[7]);
    *(float4*)pb       = make_float4(b[0], b[1], b[2], b[3]);
    *(float4*)(pb + 4) = make_float4(b[4], b[5], b[6], b[7]);
}

// ---------------- init output: out = [h ; x] ----------------
__global__ void copy_kernel(const float* __restrict__ h, const float* __restrict__ x,
                            float* __restrict__ out, int n)
{
    int i = blockIdx.x * blockDim.x + threadIdx.x;
    if (i >= n) return;
    const int NH = NN * NDIM;
    float v;
    if (i < NH)                v = h[i];
    else if (i - NH < NN * 3)  v = x[i - NH];
    else                       v = 0.f;
    out[i] = v;
}

// ---------------- edge kernel: 2 edges per warp per step, weights in smem ----------------
__global__ __launch_bounds__(256)
void edge_kernel(const float* __restrict__ edge_dist,
                 const float* __restrict__ x,
                 const float* __restrict__ We1,
                 const float* __restrict__ be1,
                 const float* __restrict__ Wn2,
                 const float* __restrict__ bn2,
                 const float* __restrict__ Wc2,
                 float* __restrict__ out_h,
                 float* __restrict__ out_x)
{
    __shared__ float sW[EDIM][CH];        // 32 KB : folded edge->hidden weights
    __shared__ float sB[CH];              //  1 KB : fused hidden bias
    __shared__ float sT[8][2][EDIM];      //  2 KB : edge-MLP hidden per warp
    __shared__ float sH[8][2][HDIM];      //  8 KB : silu'd node-hidden per warp

    const int tid = threadIdx.x;
    const int l   = tid & 31;
    const int wid = tid >> 5;

    for (int i = tid; i < EDIM * CH; i += 256) ((float*)sW)[i] = g_We2b[i];
    for (int i = tid; i < CH;        i += 256) sB[i] = g_biasH[i];
    __syncthreads();

    // hoisted per-lane constants
    const float we1  = We1[l];
    const float be1v = be1[l];
    float bh[8];
    #pragma unroll
    for (int r = 0; r < 8; r++) bh[r] = sB[l*8 + r];
    const float b2a = bn2[2*l];
    const float b2b = bn2[2*l + 1];
    float wc2v[8];
    #pragma unroll
    for (int r = 0; r < 8; r++) wc2v[r] = Wc2[(l & 15)*8 + r];   // used by lanes >= 16
    const float* w2p = Wn2 + 2*l;                                // Wn2[k][2l], [k][2l+1]

    const int ntasks = NEDGE >> 1;            // 400000 (NEDGE even)
    const int nwarps = gridDim.x * 8;
    for (int task = blockIdx.x * 8 + wid; task < ntasks; task += nwarps) {
        const int e0 = task * 2, e1 = e0 + 1;
        const int s0 = g_src[e0], d0 = g_dst[e0];
        const int s1 = g_src[e1], d1 = g_dst[e1];
        const float q0 = edge_dist[e0], q1 = edge_dist[e1];

        // edge-MLP hidden (32 comps = 32 lanes), staged to smem for broadcast
        sT[wid][0][l] = siluf(fmaf(q0, we1, be1v));
        sT[wid][1][l] = siluf(fmaf(q1, we1, be1v));
        __syncwarp();

        // prefetch node precomputes (long-latency loads issued early)
        float pa0[8], pb0[8], pa1[8], pb1[8];
        ld8(pa0, g_Pa + (size_t)s0*CH + l*8);
        ld8(pb0, g_Pb + (size_t)d0*CH + l*8);
        ld8(pa1, g_Pa + (size_t)s1*CH + l*8);
        ld8(pb1, g_Pb + (size_t)d1*CH + l*8);

        // hidden = bias + t @ We2b  (+ Pa[src] + Pb[dst] after)
        float acc0[8], acc1[8];
        #pragma unroll
        for (int r = 0; r < 8; r++) { acc0[r] = bh[r]; acc1[r] = bh[r]; }

        #pragma unroll 4
        for (int j = 0; j < EDIM; j++) {
            float w[8];
            #pragma unroll
            for (int r = 0; r < 8; r++) w[r] = sW[j][l*8 + r];
            const float v0 = sT[wid][0][j];
            const float v1 = sT[wid][1][j];
            #pragma unroll
            for (int r = 0; r < 8; r++) {
                acc0[r] = fmaf(v0, w[r], acc0[r]);
                acc1[r] = fmaf(v1, w[r], acc1[r]);
            }
        }
        #pragma unroll
        for (int r = 0; r < 8; r++) {
            acc0[r] = siluf(acc0[r] + pa0[r] + pb0[r]);
            acc1[r] = siluf(acc1[r] + pa1[r] + pb1[r]);
        }

        // stage node-hidden (cols 0..127 live on lanes 0..15)
        __syncwarp();
        if (l < 16) {
            #pragma unroll
            for (int r = 0; r < 8; r++) {
                sH[wid][0][l*8 + r] = acc0[r];
                sH[wid][1][l*8 + r] = acc1[r];
            }
        }
        __syncwarp();

        // m = silu(hidden_n) @ Wn2 + bn2 ; lane l computes output cols {2l, 2l+1}
        float m0a = b2a, m0b = b2b, m1a = b2a, m1b = b2b;
        #pragma unroll 2
        for (int k = 0; k < HDIM; k += 4) {
            const float4 h0 = *(const float4*)&sH[wid][0][k];   // broadcast
            const float4 h1 = *(const float4*)&sH[wid][1][k];
            const float2 wa = *(const float2*)(w2p + (k+0)*NDIM);
            const float2 wb = *(const float2*)(w2p + (k+1)*NDIM);
            const float2 wc = *(const float2*)(w2p + (k+2)*NDIM);
            const float2 wd = *(const float2*)(w2p + (k+3)*NDIM);
            m0a = fmaf(h0.x, wa.x, m0a); m0b = fmaf(h0.x, wa.y, m0b);
            m1a = fmaf(h1.x, wa.x, m1a); m1b = fmaf(h1.x, wa.y, m1b);
            m0a = fmaf(h0.y, wb.x, m0a); m0b = fmaf(h0.y, wb.y, m0b);
            m1a = fmaf(h1.y, wb.x, m1a); m1b = fmaf(h1.y, wb.y, m1b);
            m0a = fmaf(h0.z, wc.x, m0a); m0b = fmaf(h0.z, wc.y, m0b);
            m1a = fmaf(h1.z, wc.x, m1a); m1b = fmaf(h1.z, wc.y, m1b);
            m0a = fmaf(h0.w, wd.x, m0a); m0b = fmaf(h0.w, wd.y, m0b);
            m1a = fmaf(h1.w, wd.x, m1a); m1b = fmaf(h1.w, wd.y, m1b);
        }

        // coord_weight = silu(hidden_c) @ Wc2  (coord hidden lives on lanes 16..31)
        float c0 = 0.f, c1 = 0.f;
        if (l >= 16) {
            #pragma unroll
            for (int r = 0; r < 8; r++) {
                c0 = fmaf(acc0[r], wc2v[r], c0);
                c1 = fmaf(acc1[r], wc2v[r], c1);
            }
        }
        #pragma unroll
        for (int s = 16; s > 0; s >>= 1) {
            c0 += __shfl_xor_sync(0xffffffffu, c0, s);
            c1 += __shfl_xor_sync(0xffffffffu, c1, s);
        }

        // scatter h_agg: 4 spread REDs per lane
        atomicAdd(out_h + (size_t)d0*NDIM + 2*l,     m0a);
        atomicAdd(out_h + (size_t)d0*NDIM + 2*l + 1, m0b);
        atomicAdd(out_h + (size_t)d1*NDIM + 2*l,     m1a);
        atomicAdd(out_h + (size_t)d1*NDIM + 2*l + 1, m1b);

        // coord update (lanes 0..2 carry the 3 components)
        float dv0 = 0.f, dv1 = 0.f;
        if (l < 3) {
            dv0 = x[s0*3 + l] - x[d0*3 + l];
            dv1 = x[s1*3 + l] - x[d1*3 + l];
        }
        float ss0 = dv0*dv0, ss1 = dv1*dv1;
        ss0 += __shfl_xor_sync(0xffffffffu, ss0, 1);
        ss0 += __shfl_xor_sync(0xffffffffu, ss0, 2);
        ss1 += __shfl_xor_sync(0xffffffffu, ss1, 1);
        ss1 += __shfl_xor_sync(0xffffffffu, ss1, 2);
        if (l < 3) {
            const float inv0 = c0 / fmaxf(sqrtf(ss0), 1e-8f);
            const float inv1 = c1 / fmaxf(sqrtf(ss1), 1e-8f);
            atomicAdd(out_x + (size_t)d0*3 + l, inv0 * dv0);
            atomicAdd(out_x + (size_t)d1*3 + l, inv1 * dv1);
        }
    }
}

// ---------------- launch ----------------
extern "C" void kernel_launch(void* const* d_in, const int* in_sizes, int n_in,
                              void* d_out, int out_size)
{
    const float* h   = (const float*)d_in[0];
    const float* x   = (const float*)d_in[1];
    const void*  ei  = d_in[2];                 // int32 or int64 (runtime detected)
    const float* ed  = (const float*)d_in[3];
    const float* We1 = (const float*)d_in[4];
    const float* be1 = (const float*)d_in[5];
    const float* We2 = (const float*)d_in[6];
    const float* be2 = (const float*)d_in[7];
    const float* Wn1 = (const float*)d_in[8];
    const float* bn1 = (const float*)d_in[9];
    const float* Wn2 = (const float*)d_in[10];
    const float* bn2 = (const float*)d_in[11];
    const float* Wc1 = (const float*)d_in[12];
    const float* bc1 = (const float*)d_in[13];
    const float* Wc2 = (const float*)d_in[14];
    float* out = (float*)d_out;

    prep_kernel<<<32, 256>>>(We2, be2, Wn1, bn1, Wc1, bc1, (const int*)ei);
    index_kernel<<<(NEDGE + 255) / 256, 256>>>(ei);
    node_kernel<<<(NN * 32 + 255) / 256, 256>>>(h, Wn1, Wc1);
    copy_kernel<<<(out_size + 255) / 256, 256>>>(h, x, out, out_size);
    edge_kernel<<<1850, 256>>>(ed, x, We1, be1, Wn2, bn2, Wc2,
                               out, out + (size_t)NN * NDIM);
    (void)in_sizes; (void)n_in;
}

// round 9
// speedup vs baseline: 1.3196x; 1.3196x over previous
#include <cuda_runtime.h>
#include <cstdint>
#include <cstddef>

#define NN     50000
#define NEDGE  800000
#define NDIM   64
#define HDIM   128
#define EDIM   32
#define CH     256   // combined hidden: 128 (node MLP) + 128 (coord MLP)

typedef unsigned long long u64;

// ---------------- device scratch (static, no allocation) ----------------
__device__ __align__(16) float g_Pa[(size_t)NN * CH];  // h[n] @ W1[rows 0..63]   (src slice)
__device__ __align__(16) float g_Pb[(size_t)NN * CH];  // h[n] @ W1[rows 64..127] (dst slice)
__device__ __align__(16) float g_We2b[EDIM * CH];      // We2 @ W1[rows 128..159]
__device__ __align__(16) float g_biasH[CH];            // [bn1;bc1] + be2 @ W1_bottom
__device__ __align__(16) ulonglong2 g_W2p[64 * 32];    // K-pair packed Wn2: [t][l] = {colA,colB}
__device__ int g_src[NEDGE];
__device__ int g_dst[NEDGE];
__device__ int g_is64;

// ---------------- f32x2 packed helpers ----------------
__device__ __forceinline__ u64 pk2(float lo, float hi) {
    u64 d;
    asm("mov.b64 %0, {%1, %2};" : "=l"(d) : "r"(__float_as_uint(lo)), "r"(__float_as_uint(hi)));
    return d;
}
__device__ __forceinline__ void upk2(u64 v, float& lo, float& hi) {
    unsigned a, b;
    asm("mov.b64 {%0, %1}, %2;" : "=r"(a), "=r"(b) : "l"(v));
    lo = __uint_as_float(a); hi = __uint_as_float(b);
}
__device__ __forceinline__ u64 fma2(u64 a, u64 b, u64 c) {
    u64 d;
    asm("fma.rn.f32x2 %0, %1, %2, %3;" : "=l"(d) : "l"(a), "l"(b), "l"(c));
    return d;
}
__device__ __forceinline__ u64 add2(u64 a, u64 b) {
    u64 d;
    asm("add.rn.f32x2 %0, %1, %2;" : "=l"(d) : "l"(a), "l"(b));
    return d;
}

__device__ __forceinline__ float siluf(float v) {
    return v / (1.f + __expf(-v));
}

// ---------------- prep: fold edge-MLP layer2 into W1; pack Wn2 ----------------
__global__ void prep_kernel(const float* __restrict__ We2, const float* __restrict__ be2,
                            const float* __restrict__ Wn1, const float* __restrict__ bn1,
                            const float* __restrict__ Wc1, const float* __restrict__ bc1,
                            const float* __restrict__ Wn2,
                            const int* __restrict__ ei32)
{
    int tid = blockIdx.x * blockDim.x + threadIdx.x;   // 32 blocks * 256 = 8192 = EDIM*CH
    if (tid < EDIM * CH) {
        int j = tid >> 8;          // 0..31   edge-hidden index
        int c = tid & 255;         // 0..255  combined hidden col
        float s = 0.f;
        for (int k = 0; k < EDIM; k++) {
            float wb = (c < HDIM) ? Wn1[(2*NDIM + k) * HDIM + c]
                                  : Wc1[(2*NDIM + k) * HDIM + (c - HDIM)];
            s = fmaf(We2[j*EDIM + k], wb, s);
        }
        g_We2b[j*CH + c] = s;
        if (j == 0) {
            float b = (c < HDIM) ? bn1[c] : bc1[c - HDIM];
            for (int k = 0; k < EDIM; k++) {
                float wb = (c < HDIM) ? Wn1[(2*NDIM + k) * HDIM + c]
                                      : Wc1[(2*NDIM + k) * HDIM + (c - HDIM)];
                b = fmaf(be2[k], wb, b);
            }
            g_biasH[c] = b;
        }
    }
    if (tid < 64 * 32) {           // K-pair packed Wn2: t = k/2, lane owns cols {2l, 2l+1}
        int t = tid >> 5;
        int l = tid & 31;
        float a0 = Wn2[(2*t    ) * NDIM + 2*l    ];
        float a1 = Wn2[(2*t + 1) * NDIM + 2*l    ];
        float b0 = Wn2[(2*t    ) * NDIM + 2*l + 1];
        float b1 = Wn2[(2*t + 1) * NDIM + 2*l + 1];
        ulonglong2 v; v.x = pk2(a0, a1); v.y = pk2(b0, b1);
        g_W2p[t*32 + l] = v;
    }
    if (tid == 0) {
        // int64 vs int32: node ids < 50000 << 2^31 so int64 layout has all odd
        // 32-bit words zero; 16 random int32 ids all-zero is impossible.
        int z = 0;
        for (int i = 1; i < 32; i += 2) z |= ei32[i];
        g_is64 = (z == 0) ? 1 : 0;
    }
}

// ---------------- index normalization: any dtype -> clamped int32 ----------------
__global__ void index_kernel(const void* __restrict__ ei)
{
    int i = blockIdx.x * blockDim.x + threadIdx.x;
    if (i >= NEDGE) return;
    int s, d;
    if (g_is64) {
        const long long* p = (const long long*)ei;
        s = (int)p[i]; d = (int)p[NEDGE + i];
    } else {
        const int* p = (const int*)ei;
        s = p[i]; d = p[NEDGE + i];
    }
    g_src[i] = min(max(s, 0), NN - 1);   // defensive: never OOB
    g_dst[i] = min(max(d, 0), NN - 1);
}

// ---------------- node precompute: Pa/Pb = h @ W1(top/mid), packed f32x2 ----------------
__global__ __launch_bounds__(256)
void node_kernel(const float* __restrict__ h,
                 const float* __restrict__ Wn1,
                 const float* __restrict__ Wc1)
{
    const int node = (blockIdx.x * blockDim.x + threadIdx.x) >> 5;
    const int l = threadIdx.x & 31;
    if (node >= NN) return;

    const float h0 = h[node*NDIM + l];
    const float h1 = h[node*NDIM + 32 + l];
    // lane l owns combined cols [l*8, l*8+8): first 128 from Wn1, last 128 from Wc1
    const float* WA = (l < 16) ? (Wn1 + l*8) : (Wc1 + l*8 - HDIM);

    u64 a[4], b[4];
    #pragma unroll
    for (int r = 0; r < 4; r++) { a[r] = 0ull; b[r] = 0ull; }

    #pragma unroll 4
    for (int j = 0; j < 32; j++) {
        const float v0f = __shfl_sync(0xffffffffu, h0, j);
        const float v1f = __shfl_sync(0xffffffffu, h1, j);
        const u64 v0 = pk2(v0f, v0f);
        const u64 v1 = pk2(v1f, v1f);
        const ulonglong2* w;
        w = (const ulonglong2*)(WA + j*HDIM);              // row j      -> Pa
        { ulonglong2 p = w[0], q = w[1];
          a[0]=fma2(v0,p.x,a[0]); a[1]=fma2(v0,p.y,a[1]); a[2]=fma2(v0,q.x,a[2]); a[3]=fma2(v0,q.y,a[3]); }
        w = (const ulonglong2*)(WA + (32 + j)*HDIM);       // row 32+j   -> Pa
        { ulonglong2 p = w[0], q = w[1];
          a[0]=fma2(v1,p.x,a[0]); a[1]=fma2(v1,p.y,a[1]); a[2]=fma2(v1,q.x,a[2]); a[3]=fma2(v1,q.y,a[3]); }
        w = (const ulonglong2*)(WA + (64 + j)*HDIM);       // row 64+j   -> Pb
        { ulonglong2 p = w[0], q = w[1];
          b[0]=fma2(v0,p.x,b[0]); b[1]=fma2(v0,p.y,b[1]); b[2]=fma2(v0,q.x,b[2]); b[3]=fma2(v0,q.y,b[3]); }
        w = (const ulonglong2*)(WA + (96 + j)*HDIM);       // row 96+j   -> Pb
        { ulonglong2 p = w[0], q = w[1];
          b[0]=fma2(v1,p.x,b[0]); b[1]=fma2(v1,p.y,b[1]); b[2]=fma2(v1,q.x,b[2]); b[3]=fma2(v1,q.y,b[3]); }
    }

    ulonglong2* pa = (ulonglong2*)(g_Pa + (size_t)node*CH + l*8);
    ulonglong2* pb = (ulonglong2*)(g_Pb + (size_t)node*CH + l*8);
    ulonglong2 oa0; oa0.x = a[0]; oa0.y = a[1];
    ulonglong2 oa1; oa1.x = a[2]; oa1.y = a[3];
    ulonglong2 ob0; ob0.x = b[0]; ob0.y = b[1];
    ulonglong2 ob1; ob1.x = b[2]; ob1.y = b[3];
    pa[0] = oa0; pa[1] = oa1;
    pb[0] = ob0; pb[1] = ob1;
}

// ---------------- init output: out = [h ; x] ----------------
__global__ void copy_kernel(const float* __restrict__ h, const float* __restrict__ x,
                            float* __restrict__ out, int n)
{
    int i = blockIdx.x * blockDim.x + threadIdx.x;
    if (i >= n) return;
    const int NH = NN * NDIM;
    float v;
    if (i < NH)                v = h[i];
    else if (i - NH < NN * 3)  v = x[i - NH];
    else                       v = 0.f;
    out[i] = v;
}

// ---------------- edge kernel: 2 edges/warp, all weights in smem, f32x2 math ----------------
// dynamic smem layout (77 KB):
//   [0      , 32768) : sW   float[32][256]      folded edge->hidden weights
//   [32768  , 65536) : sW2  ulonglong2[64][32]  K-pair packed Wn2
//   [65536  , 66560) : sB   float[256]          fused hidden bias
//   [66560  , 70656) : sT2  u64[8][2][32]       packed (t,t) edge-MLP hidden per warp
//   [70656  , 78848) : sH2  u64[8][2][64]       packed K-pairs of silu'd node-hidden
#define SMEM_TOTAL 78848

__global__ __launch_bounds__(256, 2)
void edge_kernel(const float* __restrict__ edge_dist,
                 const float* __restrict__ x,
                 const float* __restrict__ We1,
                 const float* __restrict__ be1,
                 const float* __restrict__ bn2,
                 const float* __restrict__ Wc2,
                 float* __restrict__ out_h,
                 float* __restrict__ out_x)
{
    extern __shared__ __align__(16) unsigned char smem_raw[];
    float*      sW  = (float*)smem_raw;                       // [32][256]
    ulonglong2* sW2 = (ulonglong2*)(smem_raw + 32768);        // [64][32]
    float*      sB  = (float*)(smem_raw + 65536);             // [256]
    u64*        sT2 = (u64*)(smem_raw + 66560);               // [8][2][32]
    u64*        sH2 = (u64*)(smem_raw + 70656);               // [8][2][64]

    const int tid = threadIdx.x;
    const int l   = tid & 31;
    const int wid = tid >> 5;

    for (int i = tid; i < EDIM * CH; i += 256) sW[i] = g_We2b[i];
    for (int i = tid; i < 64 * 32;   i += 256) sW2[i] = g_W2p[i];
    for (int i = tid; i < CH;        i += 256) sB[i] = g_biasH[i];
    __syncthreads();

    // hoisted per-lane constants
    const float we1  = We1[l];
    const float be1v = be1[l];
    u64 bh2[4];
    {
        const u64* bp = (const u64*)(sB) + l*4;
        #pragma unroll
        for (int r = 0; r < 4; r++) bh2[r] = bp[r];
    }
    const float b2a = bn2[2*l];
    const float b2b = bn2[2*l + 1];
    u64 wc2p[4];
    {
        const u64* wp = (const u64*)Wc2 + (l & 15)*4;   // used by lanes >= 16
        #pragma unroll
        for (int r = 0; r < 4; r++) wc2p[r] = wp[r];
    }

    u64* myT0 = sT2 + (wid*2 + 0)*EDIM;
    u64* myT1 = sT2 + (wid*2 + 1)*EDIM;
    u64* myH0 = sH2 + (wid*2 + 0)*64;
    u64* myH1 = sH2 + (wid*2 + 1)*64;

    const int ntasks = NEDGE >> 1;            // 400000
    const int nwarps = gridDim.x * 8;
    for (int task = blockIdx.x * 8 + wid; task < ntasks; task += nwarps) {
        const int e0 = task * 2, e1 = e0 + 1;
        const int s0 = g_src[e0], d0 = g_dst[e0];
        const int s1 = g_src[e1], d1 = g_dst[e1];
        const float q0 = edge_dist[e0], q1 = edge_dist[e1];

        // edge-MLP hidden, stored duplicated-packed for broadcast
        {
            const float t0 = siluf(fmaf(q0, we1, be1v));
            const float t1 = siluf(fmaf(q1, we1, be1v));
            myT0[l] = pk2(t0, t0);
            myT1[l] = pk2(t1, t1);
        }
        __syncwarp();

        // prefetch node precomputes (long-latency loads issued early)
        const ulonglong2* pA0 = (const ulonglong2*)(g_Pa + (size_t)s0*CH + l*8);
        const ulonglong2* pB0 = (const ulonglong2*)(g_Pb + (size_t)d0*CH + l*8);
        const ulonglong2* pA1 = (const ulonglong2*)(g_Pa + (size_t)s1*CH + l*8);
        const ulonglong2* pB1 = (const ulonglong2*)(g_Pb + (size_t)d1*CH + l*8);
        ulonglong2 a0l = pA0[0], a0h = pA0[1];
        ulonglong2 b0l = pB0[0], b0h = pB0[1];
        ulonglong2 a1l = pA1[0], a1h = pA1[1];
        ulonglong2 b1l = pB1[0], b1h = pB1[1];

        // hidden = bias + t @ We2b (+ Pa[src] + Pb[dst])
        u64 acc0[4], acc1[4];
        #pragma unroll
        for (int r = 0; r < 4; r++) { acc0[r] = bh2[r]; acc1[r] = bh2[r]; }

        #pragma unroll 4
        for (int j = 0; j < EDIM; j++) {
            const ulonglong2* wp = (const ulonglong2*)(sW + j*CH + l*8);
            const ulonglong2 w01 = wp[0];
            const ulonglong2 w23 = wp[1];
            const u64 v0 = myT0[j];     // broadcast
            const u64 v1 = myT1[j];
            acc0[0] = fma2(v0, w01.x, acc0[0]);
            acc0[1] = fma2(v0, w01.y, acc0[1]);
            acc0[2] = fma2(v0, w23.x, acc0[2]);
            acc0[3] = fma2(v0, w23.y, acc0[3]);
            acc1[0] = fma2(v1, w01.x, acc1[0]);
            acc1[1] = fma2(v1, w01.y, acc1[1]);
            acc1[2] = fma2(v1, w23.x, acc1[2]);
            acc1[3] = fma2(v1, w23.y, acc1[3]);
        }
        acc0[0] = add2(acc0[0], add2(a0l.x, b0l.x));
        acc0[1] = add2(acc0[1], add2(a0l.y, b0l.y));
        acc0[2] = add2(acc0[2], add2(a0h.x, b0h.x));
        acc0[3] = add2(acc0[3], add2(a0h.y, b0h.y));
        acc1[0] = add2(acc1[0], add2(a1l.x, b1l.x));
        acc1[1] = add2(acc1[1], add2(a1l.y, b1l.y));
        acc1[2] = add2(acc1[2], add2(a1h.x, b1h.x));
        acc1[3] = add2(acc1[3], add2(a1h.y, b1h.y));

        // silu (scalar through MUFU, repacked)
        #pragma unroll
        for (int r = 0; r < 4; r++) {
            float lo, hi;
            upk2(acc0[r], lo, hi);
            acc0[r] = pk2(siluf(lo), siluf(hi));
            upk2(acc1[r], lo, hi);
            acc1[r] = pk2(siluf(lo), siluf(hi));
        }

        // stage node-hidden K-pairs (cols 0..127 live on lanes 0..15)
        __syncwarp();
        if (l < 16) {
            #pragma unroll
            for (int r = 0; r < 4; r++) {
                myH0[l*4 + r] = acc0[r];
                myH1[l*4 + r] = acc1[r];
            }
        }
        __syncwarp();

        // m = silu(hidden_n) @ Wn2 + bn2 via K-pair packed FMAs
        // lane l accumulates cols {2l, 2l+1}; even-k in low half, odd-k in high half
        u64 mA0 = 0ull, mB0 = 0ull, mA1 = 0ull, mB1 = 0ull;
        #pragma unroll 4
        for (int t = 0; t < 64; t++) {
            const ulonglong2 w = sW2[t*32 + l];
            const u64 hv0 = myH0[t];    // broadcast
            const u64 hv1 = myH1[t];
            mA0 = fma2(hv0, w.x, mA0);
            mB0 = fma2(hv0, w.y, mB0);
            mA1 = fma2(hv1, w.x, mA1);
            mB1 = fma2(hv1, w.y, mB1);
        }
        float m0a, m0b, m1a, m1b;
        { float lo, hi;
          upk2(mA0, lo, hi); m0a = lo + hi + b2a;
          upk2(mB0, lo, hi); m0b = lo + hi + b2b;
          upk2(mA1, lo, hi); m1a = lo + hi + b2a;
          upk2(mB1, lo, hi); m1b = lo + hi + b2b; }

        // coord_weight = silu(hidden_c) @ Wc2 (coord hidden on lanes 16..31)
        u64 ca = 0ull, cb = 0ull;
        #pragma unroll
        for (int r = 0; r < 4; r++) {
            ca = fma2(acc0[r], wc2p[r], ca);
            cb = fma2(acc1[r], wc2p[r], cb);
        }
        float c0, c1;
        { float lo, hi;
          upk2(ca, lo, hi); c0 = (l >= 16) ? (lo + hi) : 0.f;
          upk2(cb, lo, hi); c1 = (l >= 16) ? (lo + hi) : 0.f; }
        #pragma unroll
        for (int s = 16; s > 0; s >>= 1) {
            c0 += __shfl_xor_sync(0xffffffffu, c0, s);
            c1 += __shfl_xor_sync(0xffffffffu, c1, s);
        }

        // scatter h_agg: 4 spread REDs per lane
        atomicAdd(out_h + (size_t)d0*NDIM + 2*l,     m0a);
        atomicAdd(out_h + (size_t)d0*NDIM + 2*l + 1, m0b);
        atomicAdd(out_h + (size_t)d1*NDIM + 2*l,     m1a);
        atomicAdd(out_h + (size_t)d1*NDIM + 2*l + 1, m1b);

        // coord update (lanes 0..2 carry the 3 components)
        float dv0 = 0.f, dv1 = 0.f;
        if (l < 3) {
            dv0 = x[s0*3 + l] - x[d0*3 + l];
            dv1 = x[s1*3 + l] - x[d1*3 + l];
        }
        float ss0 = dv0*dv0, ss1 = dv1*dv1;
        ss0 += __shfl_xor_sync(0xffffffffu, ss0, 1);
        ss0 += __shfl_xor_sync(0xffffffffu, ss0, 2);
        ss1 += __shfl_xor_sync(0xffffffffu, ss1, 1);
        ss1 += __shfl_xor_sync(0xffffffffu, ss1, 2);
        if (l < 3) {
            const float inv0 = c0 / fmaxf(sqrtf(ss0), 1e-8f);
            const float inv1 = c1 / fmaxf(sqrtf(ss1), 1e-8f);
            atomicAdd(out_x + (size_t)d0*3 + l, inv0 * dv0);
            atomicAdd(out_x + (size_t)d1*3 + l, inv1 * dv1);
        }
    }
}

// ---------------- launch ----------------
extern "C" void kernel_launch(void* const* d_in, const int* in_sizes, int n_in,
                              void* d_out, int out_size)
{
    const float* h   = (const float*)d_in[0];
    const float* x   = (const float*)d_in[1];
    const void*  ei  = d_in[2];                 // int32 or int64 (runtime detected)
    const float* ed  = (const float*)d_in[3];
    const float* We1 = (const float*)d_in[4];
    const float* be1 = (const float*)d_in[5];
    const float* We2 = (const float*)d_in[6];
    const float* be2 = (const float*)d_in[7];
    const float* Wn1 = (const float*)d_in[8];
    const float* bn1 = (const float*)d_in[9];
    const float* Wn2 = (const float*)d_in[10];
    const float* bn2 = (const float*)d_in[11];
    const float* Wc1 = (const float*)d_in[12];
    const float* bc1 = (const float*)d_in[13];
    const float* Wc2 = (const float*)d_in[14];
    float* out = (float*)d_out;

    cudaFuncSetAttribute(edge_kernel, cudaFuncAttributeMaxDynamicSharedMemorySize, SMEM_TOTAL);

    prep_kernel<<<32, 256>>>(We2, be2, Wn1, bn1, Wc1, bc1, Wn2, (const int*)ei);
    index_kernel<<<(NEDGE + 255) / 256, 256>>>(ei);
    node_kernel<<<(NN * 32 + 255) / 256, 256>>>(h, Wn1, Wc1);
    copy_kernel<<<(out_size + 255) / 256, 256>>>(h, x, out, out_size);
    edge_kernel<<<296, 256, SMEM_TOTAL>>>(ed, x, We1, be1, bn2, Wc2,
                                          out, out + (size_t)NN * NDIM);
    (void)in_sizes; (void)n_in;
}

// round 10
// speedup vs baseline: 1.5478x; 1.1730x over previous
#include <cuda_runtime.h>
#include <cstdint>
#include <cstddef>

#define NN     50000
#define NEDGE  800000
#define NDIM   64
#define HDIM   128
#define EDIM   32
#define CH     256   // combined hidden: 128 (node MLP) + 128 (coord MLP)

typedef unsigned long long u64;

// ---------------- device scratch (static, no allocation) ----------------
__device__ __align__(16) float g_Pa[(size_t)NN * CH];  // h[n] @ W1[rows 0..63]   (src slice)
__device__ __align__(16) float g_Pb[(size_t)NN * CH];  // h[n] @ W1[rows 64..127] (dst slice)
__device__ __align__(16) float g_We2b[EDIM * CH];      // We2 @ W1[rows 128..159]
__device__ __align__(16) float g_biasH[CH];            // [bn1;bc1] + be2 @ W1_bottom
__device__ __align__(16) ulonglong2 g_W2p[64 * 32];    // K-pair packed Wn2: [t][l] = {colA,colB}
__device__ int g_src[NEDGE];
__device__ int g_dst[NEDGE];
__device__ int g_is64;

// ---------------- f32x2 packed helpers ----------------
__device__ __forceinline__ u64 pk2(float lo, float hi) {
    u64 d;
    asm("mov.b64 %0, {%1, %2};" : "=l"(d) : "r"(__float_as_uint(lo)), "r"(__float_as_uint(hi)));
    return d;
}
__device__ __forceinline__ void upk2(u64 v, float& lo, float& hi) {
    unsigned a, b;
    asm("mov.b64 {%0, %1}, %2;" : "=r"(a), "=r"(b) : "l"(v));
    lo = __uint_as_float(a); hi = __uint_as_float(b);
}
__device__ __forceinline__ u64 fma2(u64 a, u64 b, u64 c) {
    u64 d;
    asm("fma.rn.f32x2 %0, %1, %2, %3;" : "=l"(d) : "l"(a), "l"(b), "l"(c));
    return d;
}
__device__ __forceinline__ u64 add2(u64 a, u64 b) {
    u64 d;
    asm("add.rn.f32x2 %0, %1, %2;" : "=l"(d) : "l"(a), "l"(b));
    return d;
}

__device__ __forceinline__ float siluf(float v) {
    return v / (1.f + __expf(-v));
}

// ---------------- prep: fold edge-MLP layer2 into W1; pack Wn2 ----------------
__global__ void prep_kernel(const float* __restrict__ We2, const float* __restrict__ be2,
                            const float* __restrict__ Wn1, const float* __restrict__ bn1,
                            const float* __restrict__ Wc1, const float* __restrict__ bc1,
                            const float* __restrict__ Wn2,
                            const int* __restrict__ ei32)
{
    int tid = blockIdx.x * blockDim.x + threadIdx.x;   // 32 * 256 = 8192 = EDIM*CH
    if (tid < EDIM * CH) {
        int j = tid >> 8;          // 0..31   edge-hidden index
        int c = tid & 255;         // 0..255  combined hidden col
        float s = 0.f;
        for (int k = 0; k < EDIM; k++) {
            float wb = (c < HDIM) ? Wn1[(2*NDIM + k) * HDIM + c]
                                  : Wc1[(2*NDIM + k) * HDIM + (c - HDIM)];
            s = fmaf(We2[j*EDIM + k], wb, s);
        }
        g_We2b[j*CH + c] = s;
        if (j == 0) {
            float b = (c < HDIM) ? bn1[c] : bc1[c - HDIM];
            for (int k = 0; k < EDIM; k++) {
                float wb = (c < HDIM) ? Wn1[(2*NDIM + k) * HDIM + c]
                                      : Wc1[(2*NDIM + k) * HDIM + (c - HDIM)];
                b = fmaf(be2[k], wb, b);
            }
            g_biasH[c] = b;
        }
    }
    if (tid < 64 * 32) {           // K-pair packed Wn2: t = k/2, lane owns cols {2l, 2l+1}
        int t = tid >> 5;
        int l = tid & 31;
        float a0 = Wn2[(2*t    ) * NDIM + 2*l    ];
        float a1 = Wn2[(2*t + 1) * NDIM + 2*l    ];
        float b0 = Wn2[(2*t    ) * NDIM + 2*l + 1];
        float b1 = Wn2[(2*t + 1) * NDIM + 2*l + 1];
        ulonglong2 v; v.x = pk2(a0, a1); v.y = pk2(b0, b1);
        g_W2p[t*32 + l] = v;
    }
    if (tid == 0) {
        // int64 vs int32: node ids < 50000 << 2^31 so int64 layout has all odd
        // 32-bit words zero; 16 random int32 ids all-zero is impossible.
        int z = 0;
        for (int i = 1; i < 32; i += 2) z |= ei32[i];
        g_is64 = (z == 0) ? 1 : 0;
    }
}

// ---------------- index normalization: any dtype -> clamped int32 ----------------
__global__ void index_kernel(const void* __restrict__ ei)
{
    int i = blockIdx.x * blockDim.x + threadIdx.x;
    if (i >= NEDGE) return;
    int s, d;
    if (g_is64) {
        const long long* p = (const long long*)ei;
        s = (int)p[i]; d = (int)p[NEDGE + i];
    } else {
        const int* p = (const int*)ei;
        s = p[i]; d = p[NEDGE + i];
    }
    g_src[i] = min(max(s, 0), NN - 1);   // defensive: never OOB
    g_dst[i] = min(max(d, 0), NN - 1);
}

// ---------------- node precompute: Pa/Pb = h @ W1(top/mid), packed f32x2 ----------------
__global__ __launch_bounds__(256)
void node_kernel(const float* __restrict__ h,
                 const float* __restrict__ Wn1,
                 const float* __restrict__ Wc1)
{
    const int node = (blockIdx.x * blockDim.x + threadIdx.x) >> 5;
    const int l = threadIdx.x & 31;
    if (node >= NN) return;

    const float h0 = h[node*NDIM + l];
    const float h1 = h[node*NDIM + 32 + l];
    // lane l owns combined cols [l*8, l*8+8): first 128 from Wn1, last 128 from Wc1
    const float* WA = (l < 16) ? (Wn1 + l*8) : (Wc1 + l*8 - HDIM);

    u64 a[4], b[4];
    #pragma unroll
    for (int r = 0; r < 4; r++) { a[r] = 0ull; b[r] = 0ull; }

    #pragma unroll 4
    for (int j = 0; j < 32; j++) {
        const float v0f = __shfl_sync(0xffffffffu, h0, j);
        const float v1f = __shfl_sync(0xffffffffu, h1, j);
        const u64 v0 = pk2(v0f, v0f);
        const u64 v1 = pk2(v1f, v1f);
        const ulonglong2* w;
        w = (const ulonglong2*)(WA + j*HDIM);              // row j      -> Pa
        { ulonglong2 p = w[0], q = w[1];
          a[0]=fma2(v0,p.x,a[0]); a[1]=fma2(v0,p.y,a[1]); a[2]=fma2(v0,q.x,a[2]); a[3]=fma2(v0,q.y,a[3]); }
        w = (const ulonglong2*)(WA + (32 + j)*HDIM);       // row 32+j   -> Pa
        { ulonglong2 p = w[0], q = w[1];
          a[0]=fma2(v1,p.x,a[0]); a[1]=fma2(v1,p.y,a[1]); a[2]=fma2(v1,q.x,a[2]); a[3]=fma2(v1,q.y,a[3]); }
        w = (const ulonglong2*)(WA + (64 + j)*HDIM);       // row 64+j   -> Pb
        { ulonglong2 p = w[0], q = w[1];
          b[0]=fma2(v0,p.x,b[0]); b[1]=fma2(v0,p.y,b[1]); b[2]=fma2(v0,q.x,b[2]); b[3]=fma2(v0,q.y,b[3]); }
        w = (const ulonglong2*)(WA + (96 + j)*HDIM);       // row 96+j   -> Pb
        { ulonglong2 p = w[0], q = w[1];
          b[0]=fma2(v1,p.x,b[0]); b[1]=fma2(v1,p.y,b[1]); b[2]=fma2(v1,q.x,b[2]); b[3]=fma2(v1,q.y,b[3]); }
    }

    ulonglong2* pa = (ulonglong2*)(g_Pa + (size_t)node*CH + l*8);
    ulonglong2* pb = (ulonglong2*)(g_Pb + (size_t)node*CH + l*8);
    ulonglong2 oa0; oa0.x = a[0]; oa0.y = a[1];
    ulonglong2 oa1; oa1.x = a[2]; oa1.y = a[3];
    ulonglong2 ob0; ob0.x = b[0]; ob0.y = b[1];
    ulonglong2 ob1; ob1.x = b[2]; ob1.y = b[3];
    pa[0] = oa0; pa[1] = oa1;
    pb[0] = ob0; pb[1] = ob1;
}

// ---------------- init output: out = [h ; x] ----------------
__global__ void copy_kernel(const float* __restrict__ h, const float* __restrict__ x,
                            float* __restrict__ out, int n)
{
    int i = blockIdx.x * blockDim.x + threadIdx.x;
    if (i >= n) return;
    const int NH = NN * NDIM;
    float v;
    if (i < NH)                v = h[i];
    else if (i - NH < NN * 3)  v = x[i - NH];
    else                       v = 0.f;
    out[i] = v;
}

// ---------------- edge kernel: 4 edges/warp-task, weights in smem, f32x2 math ----------------
// dynamic smem layout (91,136 B):
//   [0      , 32768) : sW   float[32][256]        folded edge->hidden weights
//   [32768  , 65536) : sW2  ulonglong2[64][32]    K-pair packed Wn2
//   [65536  , 66560) : sB   float[256]            fused hidden bias
//   [66560  , 74752) : sT   u64[8][4][32]         dup-packed edge-MLP hidden per warp
//   [74752  , 91136) : sH   u64[8][4][64]         packed K-pairs of silu'd node-hidden
#define SMEM_TOTAL 91136
#define EPT 4   // edges per task

__global__ __launch_bounds__(256, 2)
void edge_kernel(const float* __restrict__ edge_dist,
                 const float* __restrict__ x,
                 const float* __restrict__ We1,
                 const float* __restrict__ be1,
                 const float* __restrict__ bn2,
                 const float* __restrict__ Wc2,
                 float* __restrict__ out_h,
                 float* __restrict__ out_x)
{
    extern __shared__ __align__(16) unsigned char smem_raw[];
    float*      sW  = (float*)smem_raw;                       // [32][256]
    ulonglong2* sW2 = (ulonglong2*)(smem_raw + 32768);        // [64][32]
    float*      sB  = (float*)(smem_raw + 65536);             // [256]
    u64*        sT  = (u64*)(smem_raw + 66560);               // [8][4][32]
    u64*        sH  = (u64*)(smem_raw + 74752);               // [8][4][64]

    const int tid = threadIdx.x;
    const int l   = tid & 31;
    const int wid = tid >> 5;

    for (int i = tid; i < EDIM * CH; i += 256) sW[i] = g_We2b[i];
    for (int i = tid; i < 64 * 32;   i += 256) sW2[i] = g_W2p[i];
    for (int i = tid; i < CH;        i += 256) sB[i] = g_biasH[i];
    __syncthreads();

    // hoisted per-lane constants
    const float we1  = We1[l];
    const float be1v = be1[l];
    u64 bh2[4];
    {
        const u64* bp = (const u64*)(sB) + l*4;
        #pragma unroll
        for (int r = 0; r < 4; r++) bh2[r] = bp[r];
    }
    const float b2a = bn2[2*l];
    const float b2b = bn2[2*l + 1];
    u64 wc2p[4];
    {
        const u64* wp = (const u64*)Wc2 + (l & 15)*4;   // used by lanes >= 16
        #pragma unroll
        for (int r = 0; r < 4; r++) wc2p[r] = wp[r];
    }

    u64* myT = sT + (size_t)wid * EPT * EDIM;     // [e][32]
    u64* myH = sH + (size_t)wid * EPT * 64;       // [e][64]

    const int ntasks = NEDGE / EPT;               // 200000
    const int nwarps = gridDim.x * 8;
    for (int task = blockIdx.x * 8 + wid; task < ntasks; task += nwarps) {
        const int e0 = task * EPT;
        int sn[EPT], dn[EPT];
        #pragma unroll
        for (int e = 0; e < EPT; e++) { sn[e] = g_src[e0 + e]; dn[e] = g_dst[e0 + e]; }

        // edge-MLP hidden, stored duplicated-packed for broadcast
        #pragma unroll
        for (int e = 0; e < EPT; e++) {
            const float t = siluf(fmaf(edge_dist[e0 + e], we1, be1v));
            myT[e*EDIM + l] = pk2(t, t);
        }
        __syncwarp();

        // accumulators (combined hidden), bias-initialized
        u64 acc[EPT][4];
        #pragma unroll
        for (int e = 0; e < EPT; e++)
            #pragma unroll
            for (int r = 0; r < 4; r++) acc[e][r] = bh2[r];

        // ---- GEMM1 first half + Pa/Pb prefetch for e0,e1 ----
        ulonglong2 a0l = ((const ulonglong2*)(g_Pa + (size_t)sn[0]*CH + l*8))[0];
        ulonglong2 a0h = ((const ulonglong2*)(g_Pa + (size_t)sn[0]*CH + l*8))[1];
        ulonglong2 b0l = ((const ulonglong2*)(g_Pb + (size_t)dn[0]*CH + l*8))[0];
        ulonglong2 b0h = ((const ulonglong2*)(g_Pb + (size_t)dn[0]*CH + l*8))[1];
        ulonglong2 a1l = ((const ulonglong2*)(g_Pa + (size_t)sn[1]*CH + l*8))[0];
        ulonglong2 a1h = ((const ulonglong2*)(g_Pa + (size_t)sn[1]*CH + l*8))[1];
        ulonglong2 b1l = ((const ulonglong2*)(g_Pb + (size_t)dn[1]*CH + l*8))[0];
        ulonglong2 b1h = ((const ulonglong2*)(g_Pb + (size_t)dn[1]*CH + l*8))[1];

        #pragma unroll 4
        for (int jj = 0; jj < 16; jj += 2) {
            const ulonglong2* wp0 = (const ulonglong2*)(sW + (jj  )*CH + l*8);
            const ulonglong2* wp1 = (const ulonglong2*)(sW + (jj+1)*CH + l*8);
            const ulonglong2 wA0 = wp0[0], wA1 = wp0[1];
            const ulonglong2 wB0 = wp1[0], wB1 = wp1[1];
            #pragma unroll
            for (int e = 0; e < EPT; e++) {
                const ulonglong2 tv = *(const ulonglong2*)&myT[e*EDIM + jj]; // broadcast, 2 j's
                acc[e][0] = fma2(tv.x, wA0.x, acc[e][0]);
                acc[e][1] = fma2(tv.x, wA0.y, acc[e][1]);
                acc[e][2] = fma2(tv.x, wA1.x, acc[e][2]);
                acc[e][3] = fma2(tv.x, wA1.y, acc[e][3]);
                acc[e][0] = fma2(tv.y, wB0.x, acc[e][0]);
                acc[e][1] = fma2(tv.y, wB0.y, acc[e][1]);
                acc[e][2] = fma2(tv.y, wB1.x, acc[e][2]);
                acc[e][3] = fma2(tv.y, wB1.y, acc[e][3]);
            }
        }

        // fold e0/e1 gathers, then prefetch e2/e3
        acc[0][0] = add2(acc[0][0], add2(a0l.x, b0l.x));
        acc[0][1] = add2(acc[0][1], add2(a0l.y, b0l.y));
        acc[0][2] = add2(acc[0][2], add2(a0h.x, b0h.x));
        acc[0][3] = add2(acc[0][3], add2(a0h.y, b0h.y));
        acc[1][0] = add2(acc[1][0], add2(a1l.x, b1l.x));
        acc[1][1] = add2(acc[1][1], add2(a1l.y, b1l.y));
        acc[1][2] = add2(acc[1][2], add2(a1h.x, b1h.x));
        acc[1][3] = add2(acc[1][3], add2(a1h.y, b1h.y));

        a0l = ((const ulonglong2*)(g_Pa + (size_t)sn[2]*CH + l*8))[0];
        a0h = ((const ulonglong2*)(g_Pa + (size_t)sn[2]*CH + l*8))[1];
        b0l = ((const ulonglong2*)(g_Pb + (size_t)dn[2]*CH + l*8))[0];
        b0h = ((const ulonglong2*)(g_Pb + (size_t)dn[2]*CH + l*8))[1];
        a1l = ((const ulonglong2*)(g_Pa + (size_t)sn[3]*CH + l*8))[0];
        a1h = ((const ulonglong2*)(g_Pa + (size_t)sn[3]*CH + l*8))[1];
        b1l = ((const ulonglong2*)(g_Pb + (size_t)dn[3]*CH + l*8))[0];
        b1h = ((const ulonglong2*)(g_Pb + (size_t)dn[3]*CH + l*8))[1];

        #pragma unroll 4
        for (int jj = 16; jj < 32; jj += 2) {
            const ulonglong2* wp0 = (const ulonglong2*)(sW + (jj  )*CH + l*8);
            const ulonglong2* wp1 = (const ulonglong2*)(sW + (jj+1)*CH + l*8);
            const ulonglong2 wA0 = wp0[0], wA1 = wp0[1];
            const ulonglong2 wB0 = wp1[0], wB1 = wp1[1];
            #pragma unroll
            for (int e = 0; e < EPT; e++) {
                const ulonglong2 tv = *(const ulonglong2*)&myT[e*EDIM + jj];
                acc[e][0] = fma2(tv.x, wA0.x, acc[e][0]);
                acc[e][1] = fma2(tv.x, wA0.y, acc[e][1]);
                acc[e][2] = fma2(tv.x, wA1.x, acc[e][2]);
                acc[e][3] = fma2(tv.x, wA1.y, acc[e][3]);
                acc[e][0] = fma2(tv.y, wB0.x, acc[e][0]);
                acc[e][1] = fma2(tv.y, wB0.y, acc[e][1]);
                acc[e][2] = fma2(tv.y, wB1.x, acc[e][2]);
                acc[e][3] = fma2(tv.y, wB1.y, acc[e][3]);
            }
        }

        acc[2][0] = add2(acc[2][0], add2(a0l.x, b0l.x));
        acc[2][1] = add2(acc[2][1], add2(a0l.y, b0l.y));
        acc[2][2] = add2(acc[2][2], add2(a0h.x, b0h.x));
        acc[2][3] = add2(acc[2][3], add2(a0h.y, b0h.y));
        acc[3][0] = add2(acc[3][0], add2(a1l.x, b1l.x));
        acc[3][1] = add2(acc[3][1], add2(a1l.y, b1l.y));
        acc[3][2] = add2(acc[3][2], add2(a1h.x, b1h.x));
        acc[3][3] = add2(acc[3][3], add2(a1h.y, b1h.y));

        // silu (scalar through MUFU, repacked)
        #pragma unroll
        for (int e = 0; e < EPT; e++)
            #pragma unroll
            for (int r = 0; r < 4; r++) {
                float lo, hi;
                upk2(acc[e][r], lo, hi);
                acc[e][r] = pk2(siluf(lo), siluf(hi));
            }

        // stage node-hidden K-pairs (cols 0..127 live on lanes 0..15)
        __syncwarp();
        if (l < 16) {
            #pragma unroll
            for (int e = 0; e < EPT; e++)
                #pragma unroll
                for (int r = 0; r < 4; r++)
                    myH[e*64 + l*4 + r] = acc[e][r];
        }
        __syncwarp();

        // ---- GEMM2: m = silu(hidden_n) @ Wn2 + bn2, K-pair packed ----
        u64 mA[EPT], mB[EPT];
        #pragma unroll
        for (int e = 0; e < EPT; e++) { mA[e] = 0ull; mB[e] = 0ull; }

        #pragma unroll 2
        for (int tp = 0; tp < 32; tp++) {
            const ulonglong2 w0 = sW2[(2*tp    )*32 + l];
            const ulonglong2 w1 = sW2[(2*tp + 1)*32 + l];
            #pragma unroll
            for (int e = 0; e < EPT; e++) {
                const ulonglong2 hv = *(const ulonglong2*)&myH[e*64 + 2*tp]; // broadcast, 2 K-pairs
                mA[e] = fma2(hv.x, w0.x, mA[e]);
                mB[e] = fma2(hv.x, w0.y, mB[e]);
                mA[e] = fma2(hv.y, w1.x, mA[e]);
                mB[e] = fma2(hv.y, w1.y, mB[e]);
            }
        }

        // ---- coord weight + scatter per edge ----
        #pragma unroll
        for (int e = 0; e < EPT; e++) {
            float lo, hi, m_a, m_b;
            upk2(mA[e], lo, hi); m_a = lo + hi + b2a;
            upk2(mB[e], lo, hi); m_b = lo + hi + b2b;

            u64 cp = 0ull;
            #pragma unroll
            for (int r = 0; r < 4; r++) cp = fma2(acc[e][r], wc2p[r], cp);
            upk2(cp, lo, hi);
            float c = (l >= 16) ? (lo + hi) : 0.f;
            #pragma unroll
            for (int s = 16; s > 0; s >>= 1)
                c += __shfl_xor_sync(0xffffffffu, c, s);

            atomicAdd(out_h + (size_t)dn[e]*NDIM + 2*l,     m_a);
            atomicAdd(out_h + (size_t)dn[e]*NDIM + 2*l + 1, m_b);

            float dv = 0.f;
            if (l < 3) dv = x[sn[e]*3 + l] - x[dn[e]*3 + l];
            float ss = dv * dv;
            ss += __shfl_xor_sync(0xffffffffu, ss, 1);
            ss += __shfl_xor_sync(0xffffffffu, ss, 2);
            if (l < 3) {
                const float inv = c / fmaxf(sqrtf(ss), 1e-8f);
                atomicAdd(out_x + (size_t)dn[e]*3 + l, inv * dv);
            }
        }
    }
}

// ---------------- launch ----------------
extern "C" void kernel_launch(void* const* d_in, const int* in_sizes, int n_in,
                              void* d_out, int out_size)
{
    const float* h   = (const float*)d_in[0];
    const float* x   = (const float*)d_in[1];
    const void*  ei  = d_in[2];                 // int32 or int64 (runtime detected)
    const float* ed  = (const float*)d_in[3];
    const float* We1 = (const float*)d_in[4];
    const float* be1 = (const float*)d_in[5];
    const float* We2 = (const float*)d_in[6];
    const float* be2 = (const float*)d_in[7];
    const float* Wn1 = (const float*)d_in[8];
    const float* bn1 = (const float*)d_in[9];
    const float* Wn2 = (const float*)d_in[10];
    const float* bn2 = (const float*)d_in[11];
    const float* Wc1 = (const float*)d_in[12];
    const float* bc1 = (const float*)d_in[13];
    const float* Wc2 = (const float*)d_in[14];
    float* out = (float*)d_out;

    cudaFuncSetAttribute(edge_kernel, cudaFuncAttributeMaxDynamicSharedMemorySize, SMEM_TOTAL);

    prep_kernel<<<32, 256>>>(We2, be2, Wn1, bn1, Wc1, bc1, Wn2, (const int*)ei);
    index_kernel<<<(NEDGE + 255) / 256, 256>>>(ei);
    node_kernel<<<(NN * 32 + 255) / 256, 256>>>(h, Wn1, Wc1);
    copy_kernel<<<(out_size + 255) / 256, 256>>>(h, x, out, out_size);
    edge_kernel<<<296, 256, SMEM_TOTAL>>>(ed, x, We1, be1, bn2, Wc2,
                                          out, out + (size_t)NN * NDIM);
    (void)in_sizes; (void)n_in;
}

// round 11
// speedup vs baseline: 1.5850x; 1.0240x over previous
#include <cuda_runtime.h>
#include <cstdint>
#include <cstddef>

#define NN     50000
#define NEDGE  800000
#define NDIM   64
#define HDIM   128
#define EDIM   32
#define CH     256   // combined hidden: 128 (node MLP) + 128 (coord MLP)

typedef unsigned long long u64;

// ---------------- device scratch (static, no allocation) ----------------
__device__ __align__(16) float g_Pa[(size_t)NN * CH];  // h[n] @ W1[rows 0..63]   (src slice)
__device__ __align__(16) float g_Pb[(size_t)NN * CH];  // h[n] @ W1[rows 64..127] (dst slice)
__device__ __align__(16) float g_We2b[EDIM * CH];      // We2 @ W1[rows 128..159]
__device__ __align__(16) float g_biasH[CH];            // [bn1;bc1] + be2 @ W1_bottom
__device__ __align__(16) ulonglong2 g_W2p[64 * 32];    // K-pair packed Wn2: [t][l] = {colA,colB}
__device__ int g_src[NEDGE];
__device__ int g_dst[NEDGE];

// ---------------- f32x2 packed helpers ----------------
__device__ __forceinline__ u64 pk2(float lo, float hi) {
    u64 d;
    asm("mov.b64 %0, {%1, %2};" : "=l"(d) : "r"(__float_as_uint(lo)), "r"(__float_as_uint(hi)));
    return d;
}
__device__ __forceinline__ void upk2(u64 v, float& lo, float& hi) {
    unsigned a, b;
    asm("mov.b64 {%0, %1}, %2;" : "=r"(a), "=r"(b) : "l"(v));
    lo = __uint_as_float(a); hi = __uint_as_float(b);
}
__device__ __forceinline__ u64 fma2(u64 a, u64 b, u64 c) {
    u64 d;
    asm("fma.rn.f32x2 %0, %1, %2, %3;" : "=l"(d) : "l"(a), "l"(b), "l"(c));
    return d;
}
__device__ __forceinline__ u64 add2(u64 a, u64 b) {
    u64 d;
    asm("add.rn.f32x2 %0, %1, %2;" : "=l"(d) : "l"(a), "l"(b));
    return d;
}

__device__ __forceinline__ float siluf(float v) {
    return v / (1.f + __expf(-v));
}

// ---------------- prep + index (merged so edge_kernel is the 4th launch) ----------------
__global__ void prep_index_kernel(const float* __restrict__ We2, const float* __restrict__ be2,
                                  const float* __restrict__ Wn1, const float* __restrict__ bn1,
                                  const float* __restrict__ Wc1, const float* __restrict__ bc1,
                                  const float* __restrict__ Wn2,
                                  const void*  __restrict__ ei)
{
    int tid = blockIdx.x * blockDim.x + threadIdx.x;

    if (tid < EDIM * CH) {         // fold edge-MLP layer2 into combined W1
        int j = tid >> 8;          // 0..31   edge-hidden index
        int c = tid & 255;         // 0..255  combined hidden col
        float s = 0.f;
        for (int k = 0; k < EDIM; k++) {
            float wb = (c < HDIM) ? Wn1[(2*NDIM + k) * HDIM + c]
                                  : Wc1[(2*NDIM + k) * HDIM + (c - HDIM)];
            s = fmaf(We2[j*EDIM + k], wb, s);
        }
        g_We2b[j*CH + c] = s;
        if (j == 0) {
            float b = (c < HDIM) ? bn1[c] : bc1[c - HDIM];
            for (int k = 0; k < EDIM; k++) {
                float wb = (c < HDIM) ? Wn1[(2*NDIM + k) * HDIM + c]
                                      : Wc1[(2*NDIM + k) * HDIM + (c - HDIM)];
                b = fmaf(be2[k], wb, b);
            }
            g_biasH[c] = b;
        }
    }
    if (tid < 64 * 32) {           // K-pair packed Wn2: t = k/2, lane owns cols {2l, 2l+1}
        int t = tid >> 5;
        int l = tid & 31;
        float a0 = Wn2[(2*t    ) * NDIM + 2*l    ];
        float a1 = Wn2[(2*t + 1) * NDIM + 2*l    ];
        float b0 = Wn2[(2*t    ) * NDIM + 2*l + 1];
        float b1 = Wn2[(2*t + 1) * NDIM + 2*l + 1];
        ulonglong2 v; v.x = pk2(a0, a1); v.y = pk2(b0, b1);
        g_W2p[t*32 + l] = v;
    }

    if (tid < NEDGE) {
        // int64 vs int32 probe, recomputed per-thread from one cached 128B line:
        // node ids < 50000 << 2^31, so int64 layout has all odd 32-bit words zero;
        // 16 random int32 ids all-zero is impossible.
        const int* w = (const int*)ei;
        int z = 0;
        #pragma unroll
        for (int i = 1; i < 32; i += 2) z |= w[i];
        int s, d;
        if (z == 0) {
            const long long* p = (const long long*)ei;
            s = (int)p[tid]; d = (int)p[NEDGE + tid];
        } else {
            s = w[tid]; d = w[NEDGE + tid];
        }
        g_src[tid] = min(max(s, 0), NN - 1);   // defensive: never OOB
        g_dst[tid] = min(max(d, 0), NN - 1);
    }
}

// ---------------- node precompute: Pa/Pb = h @ W1(top/mid), packed f32x2 ----------------
__global__ __launch_bounds__(256)
void node_kernel(const float* __restrict__ h,
                 const float* __restrict__ Wn1,
                 const float* __restrict__ Wc1)
{
    const int node = (blockIdx.x * blockDim.x + threadIdx.x) >> 5;
    const int l = threadIdx.x & 31;
    if (node >= NN) return;

    const float h0 = h[node*NDIM + l];
    const float h1 = h[node*NDIM + 32 + l];
    // lane l owns combined cols [l*8, l*8+8): first 128 from Wn1, last 128 from Wc1
    const float* WA = (l < 16) ? (Wn1 + l*8) : (Wc1 + l*8 - HDIM);

    u64 a[4], b[4];
    #pragma unroll
    for (int r = 0; r < 4; r++) { a[r] = 0ull; b[r] = 0ull; }

    #pragma unroll 4
    for (int j = 0; j < 32; j++) {
        const float v0f = __shfl_sync(0xffffffffu, h0, j);
        const float v1f = __shfl_sync(0xffffffffu, h1, j);
        const u64 v0 = pk2(v0f, v0f);
        const u64 v1 = pk2(v1f, v1f);
        const ulonglong2* w;
        w = (const ulonglong2*)(WA + j*HDIM);              // row j      -> Pa
        { ulonglong2 p = w[0], q = w[1];
          a[0]=fma2(v0,p.x,a[0]); a[1]=fma2(v0,p.y,a[1]); a[2]=fma2(v0,q.x,a[2]); a[3]=fma2(v0,q.y,a[3]); }
        w = (const ulonglong2*)(WA + (32 + j)*HDIM);       // row 32+j   -> Pa
        { ulonglong2 p = w[0], q = w[1];
          a[0]=fma2(v1,p.x,a[0]); a[1]=fma2(v1,p.y,a[1]); a[2]=fma2(v1,q.x,a[2]); a[3]=fma2(v1,q.y,a[3]); }
        w = (const ulonglong2*)(WA + (64 + j)*HDIM);       // row 64+j   -> Pb
        { ulonglong2 p = w[0], q = w[1];
          b[0]=fma2(v0,p.x,b[0]); b[1]=fma2(v0,p.y,b[1]); b[2]=fma2(v0,q.x,b[2]); b[3]=fma2(v0,q.y,b[3]); }
        w = (const ulonglong2*)(WA + (96 + j)*HDIM);       // row 96+j   -> Pb
        { ulonglong2 p = w[0], q = w[1];
          b[0]=fma2(v1,p.x,b[0]); b[1]=fma2(v1,p.y,b[1]); b[2]=fma2(v1,q.x,b[2]); b[3]=fma2(v1,q.y,b[3]); }
    }

    ulonglong2* pa = (ulonglong2*)(g_Pa + (size_t)node*CH + l*8);
    ulonglong2* pb = (ulonglong2*)(g_Pb + (size_t)node*CH + l*8);
    ulonglong2 oa0; oa0.x = a[0]; oa0.y = a[1];
    ulonglong2 oa1; oa1.x = a[2]; oa1.y = a[3];
    ulonglong2 ob0; ob0.x = b[0]; ob0.y = b[1];
    ulonglong2 ob1; ob1.x = b[2]; ob1.y = b[3];
    pa[0] = oa0; pa[1] = oa1;
    pb[0] = ob0; pb[1] = ob1;
}

// ---------------- init output: out = [h ; x] ----------------
__global__ void copy_kernel(const float* __restrict__ h, const float* __restrict__ x,
                            float* __restrict__ out, int n)
{
    int i = blockIdx.x * blockDim.x + threadIdx.x;
    if (i >= n) return;
    const int NH = NN * NDIM;
    float v;
    if (i < NH)                v = h[i];
    else if (i - NH < NN * 3)  v = x[i - NH];
    else                       v = 0.f;
    out[i] = v;
}

// ---------------- edge kernel: 4 edges/warp-task, weights in smem, f32x2 math ----------------
// dynamic smem layout (91,136 B):
//   [0      , 32768) : sW   float[32][256]        folded edge->hidden weights
//   [32768  , 65536) : sW2  ulonglong2[64][32]    K-pair packed Wn2
//   [65536  , 66560) : sB   float[256]            fused hidden bias
//   [66560  , 74752) : sT   u64[8][4][32]         dup-packed edge-MLP hidden per warp
//   [74752  , 91136) : sH   u64[8][4][64]         packed K-pairs of silu'd node-hidden
#define SMEM_TOTAL 91136
#define EPT 4   // edges per task

__global__ __launch_bounds__(256, 2)
void edge_kernel(const float* __restrict__ edge_dist,
                 const float* __restrict__ x,
                 const float* __restrict__ We1,
                 const float* __restrict__ be1,
                 const float* __restrict__ bn2,
                 const float* __restrict__ Wc2,
                 float* __restrict__ out_h,
                 float* __restrict__ out_x)
{
    extern __shared__ __align__(16) unsigned char smem_raw[];
    float*      sW  = (float*)smem_raw;                       // [32][256]
    ulonglong2* sW2 = (ulonglong2*)(smem_raw + 32768);        // [64][32]
    float*      sB  = (float*)(smem_raw + 65536);             // [256]
    u64*        sT  = (u64*)(smem_raw + 66560);               // [8][4][32]
    u64*        sH  = (u64*)(smem_raw + 74752);               // [8][4][64]

    const int tid = threadIdx.x;
    const int l   = tid & 31;
    const int wid = tid >> 5;

    for (int i = tid; i < EDIM * CH; i += 256) sW[i] = g_We2b[i];
    for (int i = tid; i < 64 * 32;   i += 256) sW2[i] = g_W2p[i];
    for (int i = tid; i < CH;        i += 256) sB[i] = g_biasH[i];
    __syncthreads();

    // hoisted per-lane constants
    const float we1  = We1[l];
    const float be1v = be1[l];
    u64 bh2[4];
    {
        const u64* bp = (const u64*)(sB) + l*4;
        #pragma unroll
        for (int r = 0; r < 4; r++) bh2[r] = bp[r];
    }
    const float b2a = bn2[2*l];
    const float b2b = bn2[2*l + 1];
    u64 wc2p[4];
    {
        const u64* wp = (const u64*)Wc2 + (l & 15)*4;   // used by lanes >= 16
        #pragma unroll
        for (int r = 0; r < 4; r++) wc2p[r] = wp[r];
    }

    u64* myT = sT + (size_t)wid * EPT * EDIM;     // [e][32]
    u64* myH = sH + (size_t)wid * EPT * 64;       // [e][64]

    const int ntasks = NEDGE / EPT;               // 200000
    const int nwarps = gridDim.x * 8;
    for (int task = blockIdx.x * 8 + wid; task < ntasks; task += nwarps) {
        const int e0 = task * EPT;
        int sn[EPT], dn[EPT];
        #pragma unroll
        for (int e = 0; e < EPT; e++) { sn[e] = g_src[e0 + e]; dn[e] = g_dst[e0 + e]; }

        // -------- cross-task software pipeline: L2-prefetch next task's gathers --------
        {
            const int nxt = task + nwarps;
            if (nxt < ntasks) {
                const int ne0 = nxt * EPT;
                #pragma unroll
                for (int e = 0; e < EPT; e++) {
                    const int ns = g_src[ne0 + e];
                    const int nd = g_dst[ne0 + e];
                    const char* pa = (const char*)(g_Pa + (size_t)ns*CH) + l*32;  // lane-sliced 1KB row
                    const char* pb = (const char*)(g_Pb + (size_t)nd*CH) + l*32;
                    asm volatile("prefetch.global.L2 [%0];" :: "l"(pa));
                    asm volatile("prefetch.global.L2 [%0];" :: "l"(pb));
                }
            }
        }

        // edge-MLP hidden, stored duplicated-packed for broadcast
        #pragma unroll
        for (int e = 0; e < EPT; e++) {
            const float t = siluf(fmaf(edge_dist[e0 + e], we1, be1v));
            myT[e*EDIM + l] = pk2(t, t);
        }
        __syncwarp();

        // accumulators (combined hidden), bias-initialized
        u64 acc[EPT][4];
        #pragma unroll
        for (int e = 0; e < EPT; e++)
            #pragma unroll
            for (int r = 0; r < 4; r++) acc[e][r] = bh2[r];

        // ---- GEMM1 first half + Pa/Pb gathers for e0,e1 (L2 hits via prefetch) ----
        ulonglong2 a0l = ((const ulonglong2*)(g_Pa + (size_t)sn[0]*CH + l*8))[0];
        ulonglong2 a0h = ((const ulonglong2*)(g_Pa + (size_t)sn[0]*CH + l*8))[1];
        ulonglong2 b0l = ((const ulonglong2*)(g_Pb + (size_t)dn[0]*CH + l*8))[0];
        ulonglong2 b0h = ((const ulonglong2*)(g_Pb + (size_t)dn[0]*CH + l*8))[1];
        ulonglong2 a1l = ((const ulonglong2*)(g_Pa + (size_t)sn[1]*CH + l*8))[0];
        ulonglong2 a1h = ((const ulonglong2*)(g_Pa + (size_t)sn[1]*CH + l*8))[1];
        ulonglong2 b1l = ((const ulonglong2*)(g_Pb + (size_t)dn[1]*CH + l*8))[0];
        ulonglong2 b1h = ((const ulonglong2*)(g_Pb + (size_t)dn[1]*CH + l*8))[1];

        #pragma unroll 4
        for (int jj = 0; jj < 16; jj += 2) {
            const ulonglong2* wp0 = (const ulonglong2*)(sW + (jj  )*CH + l*8);
            const ulonglong2* wp1 = (const ulonglong2*)(sW + (jj+1)*CH + l*8);
            const ulonglong2 wA0 = wp0[0], wA1 = wp0[1];
            const ulonglong2 wB0 = wp1[0], wB1 = wp1[1];
            #pragma unroll
            for (int e = 0; e < EPT; e++) {
                const ulonglong2 tv = *(const ulonglong2*)&myT[e*EDIM + jj]; // broadcast, 2 j's
                acc[e][0] = fma2(tv.x, wA0.x, acc[e][0]);
                acc[e][1] = fma2(tv.x, wA0.y, acc[e][1]);
                acc[e][2] = fma2(tv.x, wA1.x, acc[e][2]);
                acc[e][3] = fma2(tv.x, wA1.y, acc[e][3]);
                acc[e][0] = fma2(tv.y, wB0.x, acc[e][0]);
                acc[e][1] = fma2(tv.y, wB0.y, acc[e][1]);
                acc[e][2] = fma2(tv.y, wB1.x, acc[e][2]);
                acc[e][3] = fma2(tv.y, wB1.y, acc[e][3]);
            }
        }

        // fold e0/e1 gathers, then load e2/e3
        acc[0][0] = add2(acc[0][0], add2(a0l.x, b0l.x));
        acc[0][1] = add2(acc[0][1], add2(a0l.y, b0l.y));
        acc[0][2] = add2(acc[0][2], add2(a0h.x, b0h.x));
        acc[0][3] = add2(acc[0][3], add2(a0h.y, b0h.y));
        acc[1][0] = add2(acc[1][0], add2(a1l.x, b1l.x));
        acc[1][1] = add2(acc[1][1], add2(a1l.y, b1l.y));
        acc[1][2] = add2(acc[1][2], add2(a1h.x, b1h.x));
        acc[1][3] = add2(acc[1][3], add2(a1h.y, b1h.y));

        a0l = ((const ulonglong2*)(g_Pa + (size_t)sn[2]*CH + l*8))[0];
        a0h = ((const ulonglong2*)(g_Pa + (size_t)sn[2]*CH + l*8))[1];
        b0l = ((const ulonglong2*)(g_Pb + (size_t)dn[2]*CH + l*8))[0];
        b0h = ((const ulonglong2*)(g_Pb + (size_t)dn[2]*CH + l*8))[1];
        a1l = ((const ulonglong2*)(g_Pa + (size_t)sn[3]*CH + l*8))[0];
        a1h = ((const ulonglong2*)(g_Pa + (size_t)sn[3]*CH + l*8))[1];
        b1l = ((const ulonglong2*)(g_Pb + (size_t)dn[3]*CH + l*8))[0];
        b1h = ((const ulonglong2*)(g_Pb + (size_t)dn[3]*CH + l*8))[1];

        #pragma unroll 4
        for (int jj = 16; jj < 32; jj += 2) {
            const ulonglong2* wp0 = (const ulonglong2*)(sW + (jj  )*CH + l*8);
            const ulonglong2* wp1 = (const ulonglong2*)(sW + (jj+1)*CH + l*8);
            const ulonglong2 wA0 = wp0[0], wA1 = wp0[1];
            const ulonglong2 wB0 = wp1[0], wB1 = wp1[1];
            #pragma unroll
            for (int e = 0; e < EPT; e++) {
                const ulonglong2 tv = *(const ulonglong2*)&myT[e*EDIM + jj];
                acc[e][0] = fma2(tv.x, wA0.x, acc[e][0]);
                acc[e][1] = fma2(tv.x, wA0.y, acc[e][1]);
                acc[e][2] = fma2(tv.x, wA1.x, acc[e][2]);
                acc[e][3] = fma2(tv.x, wA1.y, acc[e][3]);
                acc[e][0] = fma2(tv.y, wB0.x, acc[e][0]);
                acc[e][1] = fma2(tv.y, wB0.y, acc[e][1]);
                acc[e][2] = fma2(tv.y, wB1.x, acc[e][2]);
                acc[e][3] = fma2(tv.y, wB1.y, acc[e][3]);
            }
        }

        acc[2][0] = add2(acc[2][0], add2(a0l.x, b0l.x));
        acc[2][1] = add2(acc[2][1], add2(a0l.y, b0l.y));
        acc[2][2] = add2(acc[2][2], add2(a0h.x, b0h.x));
        acc[2][3] = add2(acc[2][3], add2(a0h.y, b0h.y));
        acc[3][0] = add2(acc[3][0], add2(a1l.x, b1l.x));
        acc[3][1] = add2(acc[3][1], add2(a1l.y, b1l.y));
        acc[3][2] = add2(acc[3][2], add2(a1h.x, b1h.x));
        acc[3][3] = add2(acc[3][3], add2(a1h.y, b1h.y));

        // silu (scalar through MUFU, repacked)
        #pragma unroll
        for (int e = 0; e < EPT; e++)
            #pragma unroll
            for (int r = 0; r < 4; r++) {
                float lo, hi;
                upk2(acc[e][r], lo, hi);
                acc[e][r] = pk2(siluf(lo), siluf(hi));
            }

        // stage node-hidden K-pairs (cols 0..127 live on lanes 0..15)
        __syncwarp();
        if (l < 16) {
            #pragma unroll
            for (int e = 0; e < EPT; e++)
                #pragma unroll
                for (int r = 0; r < 4; r++)
                    myH[e*64 + l*4 + r] = acc[e][r];
        }
        __syncwarp();

        // ---- GEMM2: m = silu(hidden_n) @ Wn2 + bn2, K-pair packed ----
        u64 mA[EPT], mB[EPT];
        #pragma unroll
        for (int e = 0; e < EPT; e++) { mA[e] = 0ull; mB[e] = 0ull; }

        #pragma unroll 2
        for (int tp = 0; tp < 32; tp++) {
            const ulonglong2 w0 = sW2[(2*tp    )*32 + l];
            const ulonglong2 w1 = sW2[(2*tp + 1)*32 + l];
            #pragma unroll
            for (int e = 0; e < EPT; e++) {
                const ulonglong2 hv = *(const ulonglong2*)&myH[e*64 + 2*tp]; // broadcast, 2 K-pairs
                mA[e] = fma2(hv.x, w0.x, mA[e]);
                mB[e] = fma2(hv.x, w0.y, mB[e]);
                mA[e] = fma2(hv.y, w1.x, mA[e]);
                mB[e] = fma2(hv.y, w1.y, mB[e]);
            }
        }

        // ---- coord weight + scatter per edge ----
        #pragma unroll
        for (int e = 0; e < EPT; e++) {
            float lo, hi, m_a, m_b;
            upk2(mA[e], lo, hi); m_a = lo + hi + b2a;
            upk2(mB[e], lo, hi); m_b = lo + hi + b2b;

            u64 cp = 0ull;
            #pragma unroll
            for (int r = 0; r < 4; r++) cp = fma2(acc[e][r], wc2p[r], cp);
            upk2(cp, lo, hi);
            float c = (l >= 16) ? (lo + hi) : 0.f;
            #pragma unroll
            for (int s = 16; s > 0; s >>= 1)
                c += __shfl_xor_sync(0xffffffffu, c, s);

            atomicAdd(out_h + (size_t)dn[e]*NDIM + 2*l,     m_a);
            atomicAdd(out_h + (size_t)dn[e]*NDIM + 2*l + 1, m_b);

            float dv = 0.f;
            if (l < 3) dv = x[sn[e]*3 + l] - x[dn[e]*3 + l];
            float ss = dv * dv;
            ss += __shfl_xor_sync(0xffffffffu, ss, 1);
            ss += __shfl_xor_sync(0xffffffffu, ss, 2);
            if (l < 3) {
                const float inv = c / fmaxf(sqrtf(ss), 1e-8f);
                atomicAdd(out_x + (size_t)dn[e]*3 + l, inv * dv);
            }
        }
    }
}

// ---------------- launch ----------------
extern "C" void kernel_launch(void* const* d_in, const int* in_sizes, int n_in,
                              void* d_out, int out_size)
{
    const float* h   = (const float*)d_in[0];
    const float* x   = (const float*)d_in[1];
    const void*  ei  = d_in[2];                 // int32 or int64 (runtime detected)
    const float* ed  = (const float*)d_in[3];
    const float* We1 = (const float*)d_in[4];
    const float* be1 = (const float*)d_in[5];
    const float* We2 = (const float*)d_in[6];
    const float* be2 = (const float*)d_in[7];
    const float* Wn1 = (const float*)d_in[8];
    const float* bn1 = (const float*)d_in[9];
    const float* Wn2 = (const float*)d_in[10];
    const float* bn2 = (const float*)d_in[11];
    const float* Wc1 = (const float*)d_in[12];
    const float* bc1 = (const float*)d_in[13];
    const float* Wc2 = (const float*)d_in[14];
    float* out = (float*)d_out;

    cudaFuncSetAttribute(edge_kernel, cudaFuncAttributeMaxDynamicSharedMemorySize, SMEM_TOTAL);

    prep_index_kernel<<<(NEDGE + 255) / 256, 256>>>(We2, be2, Wn1, bn1, Wc1, bc1, Wn2, ei);
    node_kernel<<<(NN * 32 + 255) / 256, 256>>>(h, Wn1, Wc1);
    copy_kernel<<<(out_size + 255) / 256, 256>>>(h, x, out, out_size);
    edge_kernel<<<296, 256, SMEM_TOTAL>>>(ed, x, We1, be1, bn2, Wc2,
                                          out, out + (size_t)NN * NDIM);
    (void)in_sizes; (void)n_in;
}